// round 7
// baseline (speedup 1.0000x reference)
#include <cuda_runtime.h>
#include <cuda_fp16.h>
#include <math.h>
#include <stdint.h>

#define N_NODES 4096
#define N_EDGES 16384
#define D       64
#define BG      16
#define SLOPE   0.01f
#define NCHUNK  65              // 64 kk chunks + 1 bias chunk

// ---------------- device scratch ----------------
__device__ __half g_Bt[NCHUNK * 4096];           // [kk][f][d] transposed We2 + bias chunk
__device__ __half g_he_h[N_EDGES * D];
__device__ __half g_h_h[N_NODES * D];            // fp16 mirror of h
__device__ float g_h[N_NODES * D];
__device__ float g_agg[N_NODES * D];
__device__ float g_deg[N_NODES];
__device__ float g_Wi4[D * D * 4];
__device__ float g_Wh4[D * D * 4];
__device__ float g_q[D];
__device__ float g_e[N_NODES];
__device__ float g_a[N_NODES];
__device__ float g_emax[BG];
__device__ float g_asum[BG];
__device__ float g_rpool[BG * D];

__device__ __forceinline__ float lrelu(float x) { return x >= 0.f ? x : SLOPE * x; }
__device__ __forceinline__ float sigm(float x)  { return 1.f / (1.f + expf(-x)); }

__device__ __forceinline__ void atomicMaxF(float* addr, float v) {
    int* ai = (int*)addr;
    int old = *ai;
    while (__int_as_float(old) < v) {
        int assumed = old;
        old = atomicCAS(ai, assumed, __float_as_int(v));
        if (old == assumed) break;
    }
}

__device__ __forceinline__ void mma16816(float c[4],
                                         uint32_t a0, uint32_t a1, uint32_t a2, uint32_t a3,
                                         uint32_t b0, uint32_t b1) {
    asm volatile(
        "mma.sync.aligned.m16n8k16.row.col.f32.f16.f16.f32 "
        "{%0,%1,%2,%3}, {%4,%5,%6,%7}, {%8,%9}, {%0,%1,%2,%3};"
        : "+f"(c[0]), "+f"(c[1]), "+f"(c[2]), "+f"(c[3])
        : "r"(a0), "r"(a1), "r"(a2), "r"(a3), "r"(b0), "r"(b1));
}

__device__ __forceinline__ void ldsm_x4(uint32_t& r0, uint32_t& r1,
                                        uint32_t& r2, uint32_t& r3,
                                        const void* smem_ptr) {
    uint32_t addr;
    asm("{ .reg .u64 t; cvta.to.shared.u64 t, %1; cvt.u32.u64 %0, t; }"
        : "=r"(addr) : "l"(smem_ptr));
    asm volatile("ldmatrix.sync.aligned.m8n8.x4.shared.b16 {%0,%1,%2,%3}, [%4];"
                 : "=r"(r0), "=r"(r1), "=r"(r2), "=r"(r3) : "r"(addr));
}

__device__ __forceinline__ uint32_t smem_u32(const void* p) {
    uint32_t a;
    asm("{ .reg .u64 t; cvta.to.shared.u64 t, %1; cvt.u32.u64 %0, t; }"
        : "=r"(a) : "l"(p));
    return a;
}

#define CPA16(dst_u32, src_ptr) \
    asm volatile("cp.async.cg.shared.global [%0], [%1], 16;" :: "r"(dst_u32), "l"(src_ptr))
#define CPA_COMMIT() asm volatile("cp.async.commit_group;" ::: "memory")
#define CPA_WAIT0()  asm volatile("cp.async.wait_group 0;" ::: "memory")

__device__ __forceinline__ uint32_t hmul2u(uint32_t a, uint32_t b) {
    __half2 r = __hmul2(*(__half2*)&a, *(__half2*)&b);
    return *(uint32_t*)&r;
}

// ---------------- prep kernels ----------------

__global__ void k_zero_misc() {
    int i = blockIdx.x * blockDim.x + threadIdx.x;
    if (i < N_NODES) g_deg[i] = 0.f;
    if (i < N_NODES * D) g_agg[i] = 0.f;
}

__global__ void k_node_init(const float* __restrict__ x,
                            const float* __restrict__ W0,
                            const float* __restrict__ b0) {
    int idx = blockIdx.x * blockDim.x + threadIdx.x;
    if (idx >= N_NODES * D) return;
    int n = idx >> 6, f = idx & 63;
    float acc = b0[f];
    acc += x[n * 3 + 0] * W0[0 * D + f];
    acc += x[n * 3 + 1] * W0[1 * D + f];
    acc += x[n * 3 + 2] * W0[2 * D + f];
    float v = lrelu(acc);
    g_h[idx] = v;
    g_h_h[idx] = __float2half(v);
}

__global__ void k_edge_init(const float* __restrict__ ea,
                            const float* __restrict__ We1,
                            const float* __restrict__ be1,
                            const int* __restrict__ ei) {
    int idx = blockIdx.x * blockDim.x + threadIdx.x;
    if (idx >= N_EDGES * D) return;
    int e = idx >> 6, f = idx & 63;
    float acc = be1[f];
    acc += ea[e * 4 + 0] * We1[0 * D + f];
    acc += ea[e * 4 + 1] * We1[1 * D + f];
    acc += ea[e * 4 + 2] * We1[2 * D + f];
    acc += ea[e * 4 + 3] * We1[3 * D + f];
    g_he_h[idx] = __float2half(lrelu(acc));
    if (f == 0) {
        int dst = ei[N_EDGES + e];
        atomicAdd(&g_deg[dst], 1.f);
    }
}

// g_Bt[kk][f][d] = We2[kk][d*64+f]  (kk<64), be2[d*64+f] (kk==64)
__global__ void k_prep_bt(const float* __restrict__ We2,
                          const float* __restrict__ be2) {
    int idx = blockIdx.x * blockDim.x + threadIdx.x;
    if (idx >= NCHUNK * 4096) return;
    int kk = idx >> 12, r = idx & 4095;
    int f = r >> 6, d = r & 63;
    float v = (kk < 64) ? We2[kk * 4096 + d * 64 + f] : be2[d * 64 + f];
    g_Bt[kk * 4096 + f * 64 + d] = __float2half(v);
}

__global__ void k_prep_gru(const float* __restrict__ Wih,
                           const float* __restrict__ Whh) {
    int idx = blockIdx.x * blockDim.x + threadIdx.x;
    if (idx >= D * D * 4) return;
    int gg = idx & 3, f = (idx >> 2) & 63, k = idx >> 8;
    float vi = 0.f, vh = 0.f;
    if (gg < 3) {
        vi = Wih[(gg * 64 + f) * 64 + k];
        vh = Whh[(gg * 64 + f) * 64 + k];
    }
    g_Wi4[idx] = vi;
    g_Wh4[idx] = vh;
}

// ---------------- fused edge GEMM + scatter ----------------
// msg[e,f] = sum_{kk,d} he[e,kk] * h[src,d] * We2[kk, d*64+f]  (+ bias chunk kk=64)
// A fragments generated in registers: A[e, kk*64+d] = he[e,kk] * h[src,d].
// Block: 128 edges, 256 threads (8 warps, m16 each), N=64 full width.
__global__ void __launch_bounds__(256) k_msg_fused(const int* __restrict__ ei) {
    __shared__ __half sHe[128][72];     // he tile + bias col 64 = 1.0
    __shared__ __half sHs[128][72];     // gathered h[src]
    __shared__ __half sB[2][64][72];    // streamed B chunk [f][d], double buffered
    __shared__ int sDst[128];
    __shared__ int sSrc[128];

    int ebase = blockIdx.x * 128;
    int tid = threadIdx.x;

    if (tid < 128) {
        sSrc[tid] = ei[ebase + tid];
        sDst[tid] = ei[N_EDGES + ebase + tid];
    }
    __syncthreads();

#pragma unroll
    for (int i = 0; i < 4; i++) {
        int u = tid * 4 + i;              // 1024 uint4 = 128 rows x 8
        int row = u >> 3, ch = u & 7;
        *(uint4*)&sHe[row][ch * 8] = *(const uint4*)&g_he_h[(ebase + row) * D + ch * 8];
        *(uint4*)&sHs[row][ch * 8] = *(const uint4*)&g_h_h[sSrc[row] * D + ch * 8];
    }
    if (tid < 128) sHe[tid][64] = __float2half(1.0f);

    // preload B chunk 0
#pragma unroll
    for (int i = 0; i < 2; i++) {
        int u = tid * 2 + i;              // 512 uint4 = 64 rows x 8
        int row = u >> 3, ch = u & 7;
        CPA16(smem_u32(&sB[0][row][ch * 8]), (const char*)(g_Bt + row * 64 + ch * 8));
    }
    CPA_COMMIT();
    __syncthreads();

    int warp = tid >> 5, lane = tid & 31;
    int g = lane >> 2, tig = lane & 3;
    int a_row = (lane & 7) + ((lane & 8) ? 8 : 0);
    int a_col8 = (lane & 16) ? 8 : 0;
    int b_row = (lane & 7) + ((lane & 16) ? 8 : 0);
    int b_col8 = (lane & 8) ? 8 : 0;
    int mrow = warp * 16;

    // loop-invariant h[src] fragments: 4 k-steps (d0 = 0,16,32,48)
    uint32_t hs[4][4];
#pragma unroll
    for (int s = 0; s < 4; s++)
        ldsm_x4(hs[s][0], hs[s][1], hs[s][2], hs[s][3],
                &sHs[mrow + a_row][s * 16 + a_col8]);

    float c[8][4];
#pragma unroll
    for (int j = 0; j < 8; j++) { c[j][0] = c[j][1] = c[j][2] = c[j][3] = 0.f; }

    for (int kk = 0; kk < NCHUNK; kk++) {
        int cur = kk & 1;
        CPA_WAIT0();
        __syncthreads();   // chunk kk visible; prev compute on buf[1-cur] done everywhere
        if (kk + 1 < NCHUNK) {
#pragma unroll
            for (int i = 0; i < 2; i++) {
                int u = tid * 2 + i;
                int row = u >> 3, ch = u & 7;
                CPA16(smem_u32(&sB[1 - cur][row][ch * 8]),
                      (const char*)(g_Bt + (size_t)(kk + 1) * 4096 + row * 64 + ch * 8));
            }
            CPA_COMMIT();
        }

        __half he0 = sHe[mrow + g][kk];
        __half he1 = sHe[mrow + g + 8][kk];
        __half2 he0p = __half2half2(he0);
        __half2 he1p = __half2half2(he1);
        uint32_t he0u = *(uint32_t*)&he0p;
        uint32_t he1u = *(uint32_t*)&he1p;

#pragma unroll
        for (int s = 0; s < 4; s++) {
            uint32_t a0 = hmul2u(he0u, hs[s][0]);
            uint32_t a1 = hmul2u(he1u, hs[s][1]);
            uint32_t a2 = hmul2u(he0u, hs[s][2]);
            uint32_t a3 = hmul2u(he1u, hs[s][3]);
#pragma unroll
            for (int jp = 0; jp < 4; jp++) {
                uint32_t b0, b1, b2, b3;
                ldsm_x4(b0, b1, b2, b3,
                        &sB[cur][jp * 16 + b_row][s * 16 + b_col8]);
                mma16816(c[2 * jp],     a0, a1, a2, a3, b0, b1);
                mma16816(c[2 * jp + 1], a0, a1, a2, a3, b2, b3);
            }
        }
    }

    // scatter to agg
    int e0 = mrow + g;
    int e1 = e0 + 8;
    int dst0 = sDst[e0], dst1 = sDst[e1];
#pragma unroll
    for (int j = 0; j < 8; j++) {
        int col = j * 8 + 2 * tig;
        atomicAdd(&g_agg[dst0 * D + col],     c[j][0]);
        atomicAdd(&g_agg[dst0 * D + col + 1], c[j][1]);
        atomicAdd(&g_agg[dst1 * D + col],     c[j][2]);
        atomicAdd(&g_agg[dst1 * D + col + 1], c[j][3]);
    }
}

// ---------------- node update ----------------
__global__ void k_node_update(const float* __restrict__ root,
                              const float* __restrict__ conv_b,
                              const float* __restrict__ bih,
                              const float* __restrict__ bhh) {
    __shared__ float sh[16][D];
    __shared__ float sm[16][D];
    __shared__ float sroot[D][D];
    int nb = blockIdx.x * 16;
    int tid = threadIdx.x;
    int f = tid & 63, ng = tid >> 6;

#pragma unroll
    for (int i = 0; i < 4; i++) {
        int ln = ng + 4 * i;
        sh[ln][f] = g_h[(nb + ln) * D + f];
    }
#pragma unroll
    for (int i = 0; i < 16; i++) {
        int idx = tid + i * 256;
        sroot[idx >> 6][idx & 63] = root[idx];
    }
    __syncthreads();

    float cb = conv_b[f];
#pragma unroll
    for (int i = 0; i < 4; i++) {
        int ln = ng + 4 * i;
        int n = nb + ln;
        float invd = 1.f / fmaxf(g_deg[n], 1.f);
        float acc = g_agg[n * D + f] * invd + cb;
        g_agg[n * D + f] = 0.f;
#pragma unroll 8
        for (int d = 0; d < D; d++) acc += sh[ln][d] * sroot[d][f];
        sm[ln][f] = lrelu(acc);
    }
    __syncthreads();

    float gir[4], giz[4], gin[4], ghr[4], ghz[4], ghn[4];
    float bir = bih[f], biz = bih[D + f], bin = bih[2 * D + f];
    float bhr = bhh[f], bhz = bhh[D + f], bhn = bhh[2 * D + f];
#pragma unroll
    for (int i = 0; i < 4; i++) {
        gir[i] = bir; giz[i] = biz; gin[i] = bin;
        ghr[i] = bhr; ghz[i] = bhz; ghn[i] = bhn;
    }

#pragma unroll 4
    for (int k = 0; k < D; k++) {
        float4 wi = *(const float4*)&g_Wi4[(k * D + f) * 4];
        float4 wh = *(const float4*)&g_Wh4[(k * D + f) * 4];
#pragma unroll
        for (int i = 0; i < 4; i++) {
            int ln = ng + 4 * i;
            float mk = sm[ln][k];
            float hk = sh[ln][k];
            gir[i] += mk * wi.x; giz[i] += mk * wi.y; gin[i] += mk * wi.z;
            ghr[i] += hk * wh.x; ghz[i] += hk * wh.y; ghn[i] += hk * wh.z;
        }
    }

#pragma unroll
    for (int i = 0; i < 4; i++) {
        int ln = ng + 4 * i;
        float r  = sigm(gir[i] + ghr[i]);
        float z  = sigm(giz[i] + ghz[i]);
        float nn = tanhf(gin[i] + r * ghn[i]);
        float hv = (1.f - z) * nn + z * sh[ln][f];
        g_h[(nb + ln) * D + f] = hv;
        g_h_h[(nb + ln) * D + f] = __float2half(hv);
    }
}

// ---------------- set2set + head ----------------

__global__ void k_s2s_init(const float* __restrict__ lbih,
                           const float* __restrict__ lbhh) {
    int t = threadIdx.x;
    if (t < D) {
        float gi = lbih[t]         + lbhh[t];
        float gg = lbih[2 * D + t] + lbhh[2 * D + t];
        float go = lbih[3 * D + t] + lbhh[3 * D + t];
        float cl = sigm(gi) * tanhf(gg);
        g_q[t] = sigm(go) * tanhf(cl);
    }
    if (t < BG) { g_emax[t] = -3.4e38f; g_asum[t] = 0.f; }
    for (int i = t; i < BG * D; i += blockDim.x) g_rpool[i] = 0.f;
}

__global__ void k_dot(const int* __restrict__ batch) {
    int lane = threadIdx.x & 31;
    int warp = threadIdx.x >> 5;
    int n = blockIdx.x * 8 + warp;
    if (n >= N_NODES) return;
    float v = g_h[n * D + lane] * g_q[lane] + g_h[n * D + 32 + lane] * g_q[32 + lane];
#pragma unroll
    for (int o = 16; o > 0; o >>= 1) v += __shfl_down_sync(0xFFFFFFFFu, v, o);
    if (lane == 0) {
        g_e[n] = v;
        atomicMaxF(&g_emax[batch[n]], v);
    }
}

__global__ void k_exp(const int* __restrict__ batch) {
    int n = blockIdx.x * blockDim.x + threadIdx.x;
    if (n >= N_NODES) return;
    int g = batch[n];
    float a = expf(g_e[n] - g_emax[g]);
    g_a[n] = a;
    atomicAdd(&g_asum[g], a);
}

__global__ void k_pool(const int* __restrict__ batch) {
    int idx = blockIdx.x * blockDim.x + threadIdx.x;
    if (idx >= N_NODES * D) return;
    int n = idx >> 6, f = idx & 63;
    int g = batch[n];
    float w = g_a[n] / g_asum[g];
    atomicAdd(&g_rpool[g * D + f], w * g_h[idx]);
}

__global__ void k_out(const float* __restrict__ Wout,
                      const float* __restrict__ bout,
                      float* __restrict__ out) {
    int t = threadIdx.x;
    if (t >= BG * 2) return;
    int b = t >> 1, c = t & 1;
    float acc = bout[c];
#pragma unroll 8
    for (int j = 0; j < D; j++) {
        acc += g_q[j] * Wout[j * 2 + c];
        acc += g_rpool[b * D + j] * Wout[(D + j) * 2 + c];
    }
    out[b * 2 + c] = acc;
}

// ---------------- launch ----------------

extern "C" void kernel_launch(void* const* d_in, const int* in_sizes, int n_in,
                              void* d_out, int out_size) {
    const float* x      = (const float*)d_in[0];
    const float* ea     = (const float*)d_in[1];
    const int*   ei     = (const int*)d_in[2];
    const int*   batch  = (const int*)d_in[3];
    const float* W0     = (const float*)d_in[4];
    const float* b0     = (const float*)d_in[5];
    const float* We1    = (const float*)d_in[6];
    const float* be1    = (const float*)d_in[7];
    const float* We2    = (const float*)d_in[8];
    const float* be2    = (const float*)d_in[9];
    const float* root   = (const float*)d_in[10];
    const float* conv_b = (const float*)d_in[11];
    const float* Wih    = (const float*)d_in[12];
    const float* Whh    = (const float*)d_in[13];
    const float* bih    = (const float*)d_in[14];
    const float* bhh    = (const float*)d_in[15];
    const float* lbih   = (const float*)d_in[18];
    const float* lbhh   = (const float*)d_in[19];
    const float* Wout   = (const float*)d_in[20];
    const float* bout   = (const float*)d_in[21];
    float* out = (float*)d_out;
    (void)in_sizes; (void)n_in; (void)out_size;

    k_zero_misc<<<(N_NODES * D) / 256, 256>>>();
    k_node_init<<<(N_NODES * D) / 256, 256>>>(x, W0, b0);
    k_edge_init<<<(N_EDGES * D) / 256, 256>>>(ea, We1, be1, ei);
    k_prep_bt<<<(NCHUNK * 4096) / 256, 256>>>(We2, be2);
    k_prep_gru<<<(D * D * 4) / 256, 256>>>(Wih, Whh);

    for (int it = 0; it < 6; it++) {
        k_msg_fused<<<N_EDGES / 128, 256>>>(ei);
        k_node_update<<<N_NODES / 16, 256>>>(root, conv_b, bih, bhh);
    }

    k_s2s_init<<<1, 256>>>(lbih, lbhh);
    k_dot<<<N_NODES / 8, 256>>>(batch);
    k_exp<<<(N_NODES + 255) / 256, 256>>>(batch);
    k_pool<<<(N_NODES * D) / 256, 256>>>(batch);
    k_out<<<1, 64>>>(Wout, bout, out);
}